// round 5
// baseline (speedup 1.0000x reference)
#include <cuda_runtime.h>

// CostVolume: B=4, C=32, Cr=16, H=64, W=128, D=48
// out[b, ch, d, h, w]:
//   ch in [0,32):   0.25*(left[b,ch,h,w]-right[b,ch,h,w-d])^2   if w>=d else 0
//   ch in [32,48):  reduce_left[b,ch-32,h,w]                     if w>=d else 0
//   ch in [48,64):  reduce_right[b,ch-48,h,w-d]                  if w>=d else 0
//
// Register-resident rows + shuffle sliding window over d.
// 2 h-rows per CTA: shared mask predicates, 1KB contiguous writes per (warp,d).
// Stores use st.global.cs (evict-first streaming; output is write-once).

#define BB 4
#define CC 32
#define CRR 16
#define HH 64
#define WW 128
#define DD 48
#define CH_TOTAL 64   // C + 2*Cr
#define HW (HH * WW)

__device__ __forceinline__ void store_cs(float* p, float4 v) {
    asm volatile("st.global.cs.v4.f32 [%0], {%1,%2,%3,%4};"
                 :: "l"(p), "f"(v.x), "f"(v.y), "f"(v.z), "f"(v.w) : "memory");
}

// Gather row[4*lane + shift] from warp-resident row (r.x..r.w per lane).
// 'shift' is warp-uniform => sub-select is uniform; shfl does lane move.
__device__ __forceinline__ float warp_gather(const float4 r, int shift, int lane) {
    const int e   = (lane << 2) + shift;
    const int lp  = (e >> 2) & 31;
    const int sub = shift & 3;
    float v;
    if      (sub == 0) v = r.x;
    else if (sub == 1) v = r.y;
    else if (sub == 2) v = r.z;
    else               v = r.w;
    return __shfl_sync(0xffffffffu, v, lp);
}

__global__ __launch_bounds__(256, 6) void cost_volume_kernel(
    const float* __restrict__ left,
    const float* __restrict__ rleft,
    const float* __restrict__ right,
    const float* __restrict__ rright,
    float* __restrict__ out)
{
    const int blk  = blockIdx.x;               // b*CH_TOTAL*(H/2) + ch*(H/2) + hp
    const int hp   = blk % (HH / 2);
    const int h    = hp << 1;                  // rows h, h+1
    const int tmp  = blk / (HH / 2);
    const int ch   = tmp % CH_TOTAL;
    const int b    = tmp / CH_TOTAL;
    const int lane = threadIdx.x & 31;
    const int warp = threadIdx.x >> 5;
    const int w0   = lane << 2;
    const int d0   = warp * 6;                 // this warp covers d in [d0, d0+6)

    float* op = out + ((size_t)(b * CH_TOTAL + ch) * DD + d0) * HW + (size_t)h * WW + w0;

    if (ch < CC) {
        const float* lbase = left  + ((b * CC + ch) * HH + h) * WW + w0;
        const float* rbase = right + ((b * CC + ch) * HH + h) * WW + w0;
        const float4 A0 = *(const float4*)(lbase);
        const float4 A1 = *(const float4*)(lbase + WW);
        const float4 R0 = *(const float4*)(rbase);
        const float4 R1 = *(const float4*)(rbase + WW);

        float u0 = warp_gather(R0, 0 - d0, lane), v0 = warp_gather(R1, 0 - d0, lane);
        float u1 = warp_gather(R0, 1 - d0, lane), v1 = warp_gather(R1, 1 - d0, lane);
        float u2 = warp_gather(R0, 2 - d0, lane), v2 = warp_gather(R1, 2 - d0, lane);
        float u3 = warp_gather(R0, 3 - d0, lane), v3 = warp_gather(R1, 3 - d0, lane);

        #pragma unroll
        for (int s = 0; s < 6; s++) {
            const int d = d0 + s;
            const bool p0 = (w0     >= d);
            const bool p1 = (w0 + 1 >= d);
            const bool p2 = (w0 + 2 >= d);
            const bool p3 = (w0 + 3 >= d);
            float4 o0, o1; float t;
            t = A0.x - u0; o0.x = p0 ? 0.25f * t * t : 0.0f;
            t = A0.y - u1; o0.y = p1 ? 0.25f * t * t : 0.0f;
            t = A0.z - u2; o0.z = p2 ? 0.25f * t * t : 0.0f;
            t = A0.w - u3; o0.w = p3 ? 0.25f * t * t : 0.0f;
            t = A1.x - v0; o1.x = p0 ? 0.25f * t * t : 0.0f;
            t = A1.y - v1; o1.y = p1 ? 0.25f * t * t : 0.0f;
            t = A1.z - v2; o1.z = p2 ? 0.25f * t * t : 0.0f;
            t = A1.w - v3; o1.w = p3 ? 0.25f * t * t : 0.0f;
            store_cs(op, o0);
            store_cs(op + WW, o1);
            op += HW;

            const float nu = warp_gather(R0, -(d + 1), lane);
            const float nv = warp_gather(R1, -(d + 1), lane);
            u3 = u2; u2 = u1; u1 = u0; u0 = nu;
            v3 = v2; v2 = v1; v1 = v0; v0 = nv;
        }
    } else if (ch < CC + CRR) {
        const float* base = rleft + ((b * CRR + (ch - CC)) * HH + h) * WW + w0;
        const float4 A0 = *(const float4*)(base);
        const float4 A1 = *(const float4*)(base + WW);
        #pragma unroll
        for (int s = 0; s < 6; s++) {
            const int d = d0 + s;
            const bool p0 = (w0     >= d);
            const bool p1 = (w0 + 1 >= d);
            const bool p2 = (w0 + 2 >= d);
            const bool p3 = (w0 + 3 >= d);
            float4 o0, o1;
            o0.x = p0 ? A0.x : 0.0f;  o1.x = p0 ? A1.x : 0.0f;
            o0.y = p1 ? A0.y : 0.0f;  o1.y = p1 ? A1.y : 0.0f;
            o0.z = p2 ? A0.z : 0.0f;  o1.z = p2 ? A1.z : 0.0f;
            o0.w = p3 ? A0.w : 0.0f;  o1.w = p3 ? A1.w : 0.0f;
            store_cs(op, o0);
            store_cs(op + WW, o1);
            op += HW;
        }
    } else {
        const float* base = rright + ((b * CRR + (ch - CC - CRR)) * HH + h) * WW + w0;
        const float4 R0 = *(const float4*)(base);
        const float4 R1 = *(const float4*)(base + WW);

        float u0 = warp_gather(R0, 0 - d0, lane), v0 = warp_gather(R1, 0 - d0, lane);
        float u1 = warp_gather(R0, 1 - d0, lane), v1 = warp_gather(R1, 1 - d0, lane);
        float u2 = warp_gather(R0, 2 - d0, lane), v2 = warp_gather(R1, 2 - d0, lane);
        float u3 = warp_gather(R0, 3 - d0, lane), v3 = warp_gather(R1, 3 - d0, lane);

        #pragma unroll
        for (int s = 0; s < 6; s++) {
            const int d = d0 + s;
            const bool p0 = (w0     >= d);
            const bool p1 = (w0 + 1 >= d);
            const bool p2 = (w0 + 2 >= d);
            const bool p3 = (w0 + 3 >= d);
            float4 o0, o1;
            o0.x = p0 ? u0 : 0.0f;  o1.x = p0 ? v0 : 0.0f;
            o0.y = p1 ? u1 : 0.0f;  o1.y = p1 ? v1 : 0.0f;
            o0.z = p2 ? u2 : 0.0f;  o1.z = p2 ? v2 : 0.0f;
            o0.w = p3 ? u3 : 0.0f;  o1.w = p3 ? v3 : 0.0f;
            store_cs(op, o0);
            store_cs(op + WW, o1);
            op += HW;

            const float nu = warp_gather(R0, -(d + 1), lane);
            const float nv = warp_gather(R1, -(d + 1), lane);
            u3 = u2; u2 = u1; u1 = u0; u0 = nu;
            v3 = v2; v2 = v1; v1 = v0; v0 = nv;
        }
    }
}

extern "C" void kernel_launch(void* const* d_in, const int* in_sizes, int n_in,
                              void* d_out, int out_size) {
    const float* left   = (const float*)d_in[0];
    const float* rleft  = (const float*)d_in[1];
    const float* right  = (const float*)d_in[2];
    const float* rright = (const float*)d_in[3];
    // d_in[4] = max_disp (int scalar) == 48, baked in as DD.

    const int grid = BB * CH_TOTAL * (HH / 2);   // 8192 CTAs
    cost_volume_kernel<<<grid, 256>>>(left, rleft, right, rright, (float*)d_out);
}